// round 2
// baseline (speedup 1.0000x reference)
#include <cuda_runtime.h>

// x: (B=8, ns=4, D=512, nc=64) fp32
// out: concat(map_hidden, map_mask), each (B, D, 4, 64, 65) fp32.
// Per (b,d): region of 4*64*65 = 16640 floats per half.
// For rel, base=1<<rel: out[rel,i,j] = runmax(x[rel, i .. i+(j-i)/base-1])
// when i%base==0, (j-i)%base==0, i<j<64; else 0. Mask = 1 at hits.
//
// Key insight: the (hit, shared-index) pattern per float4 chunk is identical
// for every (b,d). Precompute a uint16 gather-index table once per launch;
// sentinel index ZSLOT points at a zero entry in shared memory.

#define B_DIM 8
#define D_DIM 512
#define NC 64
#define NJ 65
#define REGION (4 * NC * NJ)       // 16640 floats per half per (b,d)
#define NCHUNK (REGION / 4)        // 4160 float4 chunks
#define SROWS 120                  // 64+32+16+8 running-max rows
#define ZSLOT (SROWS * NC)         // 7680: zero slot (word index into Sf)

__device__ unsigned short g_tbl[NCHUNK * 4];

__global__ void build_table_kernel() {
    int q = blockIdx.x * blockDim.x + threadIdx.x;
    if (q >= NCHUNK) return;
    int rel = q / 1040;                  // 1040 chunks per rel block
    int er  = (q - rel * 1040) << 2;     // element offset within rel block
    int i   = er / 65;
    int j   = er - i * 65;
    int bm   = (1 << rel) - 1;
    int rowb = 128 - (128 >> rel);       // 0, 64, 96, 112

    #pragma unroll
    for (int l = 0; l < 4; l++) {
        int jj = j + l;
        int ii = i;
        if (jj >= NJ) { jj -= NJ; ii += 1; }     // at most one row wrap
        bool hit = (jj > ii) && (jj < NC) &&
                   ((ii & bm) == 0) && (((jj - ii) & bm) == 0);
        unsigned short idx = (unsigned short)ZSLOT;
        if (hit) {
            int k = (jj - ii) >> rel;            // window length
            idx = (unsigned short)((rowb + (ii >> rel)) * NC + ii + k - 1);
        }
        g_tbl[q * 4 + l] = idx;
    }
}

__global__ __launch_bounds__(256, 1)
void prop3d_kernel(const float* __restrict__ x, float* __restrict__ out,
                   long half_elems) {
    __shared__ float xs[4][NC];          // input slice
    __shared__ float Sf[ZSLOT + 4];      // flat running-max table + zero slot

    const int bd  = blockIdx.x;          // b*512 + d
    const int b   = bd >> 9;
    const int d   = bd & 511;
    const int tid = threadIdx.x;

    // ---- load x[b, rel, d, :] for rel = 0..3 ----
    {
        int rel = tid >> 6;
        int c   = tid & 63;
        xs[rel][c] = x[((((b << 2) + rel) * D_DIM) + d) * NC + c];
    }
    if (tid == 255) Sf[ZSLOT] = 0.0f;
    __syncthreads();

    // ---- build running-max rows (only i multiples of base) ----
    // rel0: rows 0..63 (i=r); rel1: 64..95 (i=2(r-64));
    // rel2: 96..111 (i=4(r-96)); rel3: 112..119 (i=8(r-112))
    if (tid < SROWS) {
        int rel, i;
        if (tid < 64)       { rel = 0; i = tid; }
        else if (tid < 96)  { rel = 1; i = (tid - 64) << 1; }
        else if (tid < 112) { rel = 2; i = (tid - 96) << 2; }
        else                { rel = 3; i = (tid - 112) << 3; }
        float m = xs[rel][i];
        Sf[tid * NC + i] = m;
        for (int e = i + 1; e < NC; e++) {
            m = fmaxf(m, xs[rel][e]);
            Sf[tid * NC + e] = m;
        }
    }
    __syncthreads();

    // ---- branch-free write loop driven by the precomputed index table ----
    float4* __restrict__ hid = reinterpret_cast<float4*>(out + (long)bd * REGION);
    float4* __restrict__ msk = reinterpret_cast<float4*>(out + (long)bd * REGION + half_elems);
    const ushort4* __restrict__ tb = reinterpret_cast<const ushort4*>(g_tbl);

    #pragma unroll 2
    for (int q = tid; q < NCHUNK; q += 256) {
        ushort4 t = tb[q];
        float4 h, m;
        h.x = Sf[t.x];  m.x = (t.x != ZSLOT) ? 1.0f : 0.0f;
        h.y = Sf[t.y];  m.y = (t.y != ZSLOT) ? 1.0f : 0.0f;
        h.z = Sf[t.z];  m.z = (t.z != ZSLOT) ? 1.0f : 0.0f;
        h.w = Sf[t.w];  m.w = (t.w != ZSLOT) ? 1.0f : 0.0f;
        hid[q] = h;
        msk[q] = m;
    }
}

extern "C" void kernel_launch(void* const* d_in, const int* in_sizes, int n_in,
                              void* d_out, int out_size) {
    const float* x = (const float*)d_in[0];
    float* out = (float*)d_out;
    long half = (long)out_size / 2;      // map_hidden elements; map_mask follows

    build_table_kernel<<<(NCHUNK + 255) / 256, 256>>>();
    prop3d_kernel<<<B_DIM * D_DIM, 256>>>(x, out, half);
}